// round 2
// baseline (speedup 1.0000x reference)
#include <cuda_runtime.h>
#include <cstdint>

#define POOL 14
#define IMG_H 200
#define IMG_W 200
#define IMG_C 1024
#define NUM_ROIS 512

#define NCHUNK 4                      // channel chunks; 1024/4 = 256 ch = 41MB slice, fits L2
#define CHUNK_FLOATS (IMG_C / NCHUNK) // 256 floats
#define THREADS (CHUNK_FLOATS / 4)    // 64 threads, float4 each

// grid = (cells, NCHUNK). Chunk is the outer (slowest-varying) dim so all cells
// of one channel slice stream through before the next slice -> the 41MB image
// slice stays L2-resident and inter-ROI reads hit L2 instead of HBM.
__global__ void __launch_bounds__(THREADS, 32)
roi_resize_kernel(const float* __restrict__ img,
                  const int* __restrict__ rois,
                  float* __restrict__ out)
{
    const int idx  = blockIdx.x;                 // 0 .. 512*196-1
    const int roi  = idx / (POOL * POOL);
    const int cell = idx - roi * (POOL * POOL);
    const int py   = cell / POOL;
    const int px   = cell - py * POOL;

    const int chunk_off = blockIdx.y * CHUNK_FLOATS;   // channel offset (floats)

    // rois layout: [roi][4] = {x, y, w, h}, int32
    const int4 box = reinterpret_cast<const int4*>(rois)[roi];
    const int bx = box.x, by = box.y, bw = box.z, bh = box.w;

    // Match reference math: fraction from UNclipped floor.
    const float sy = (float)py * ((float)bh / (float)POOL);
    const float sx = (float)px * ((float)bw / (float)POOL);
    const int y0 = (int)floorf(sy);
    const int x0 = (int)floorf(sx);
    const float wy = sy - (float)y0;
    const float wx = sx - (float)x0;

    const int y0c = min(max(y0, 0), bh - 1);
    const int y1c = min(max(y0 + 1, 0), bh - 1);
    const int x0c = min(max(x0, 0), bw - 1);
    const int x1c = min(max(x0 + 1, 0), bw - 1);

    const int iy0 = by + y0c;
    const int iy1 = by + y1c;
    const int ix0 = bx + x0c;
    const int ix1 = bx + x1c;

    const float* base = img + chunk_off;
    const float4* __restrict__ p00 =
        reinterpret_cast<const float4*>(base + ((size_t)iy0 * IMG_W + ix0) * IMG_C);
    const float4* __restrict__ p01 =
        reinterpret_cast<const float4*>(base + ((size_t)iy0 * IMG_W + ix1) * IMG_C);
    const float4* __restrict__ p10 =
        reinterpret_cast<const float4*>(base + ((size_t)iy1 * IMG_W + ix0) * IMG_C);
    const float4* __restrict__ p11 =
        reinterpret_cast<const float4*>(base + ((size_t)iy1 * IMG_W + ix1) * IMG_C);

    float4* __restrict__ o =
        reinterpret_cast<float4*>(out + (size_t)idx * IMG_C + chunk_off);

    const int c = threadIdx.x;   // 0..63 -> float4 lane within chunk

    const float4 g00 = p00[c];
    const float4 g01 = p01[c];
    const float4 g10 = p10[c];
    const float4 g11 = p11[c];

    float4 r;
    {
        float top, bot;
        top = g00.x + (g01.x - g00.x) * wx;
        bot = g10.x + (g11.x - g10.x) * wx;
        r.x = top + (bot - top) * wy;
        top = g00.y + (g01.y - g00.y) * wx;
        bot = g10.y + (g11.y - g10.y) * wx;
        r.y = top + (bot - top) * wy;
        top = g00.z + (g01.z - g00.z) * wx;
        bot = g10.z + (g11.z - g10.z) * wx;
        r.z = top + (bot - top) * wy;
        top = g00.w + (g01.w - g00.w) * wx;
        bot = g10.w + (g11.w - g10.w) * wx;
        r.w = top + (bot - top) * wy;
    }
    // Streaming store: evict-first so the output stream doesn't pollute the
    // L2-resident image slice.
    __stcs(o + c, r);
}

extern "C" void kernel_launch(void* const* d_in, const int* in_sizes, int n_in,
                              void* d_out, int out_size)
{
    const float* img  = (const float*)d_in[0];
    const int*   rois = (const int*)d_in[1];
    if (in_sizes[0] == NUM_ROIS * 4) {  // defensive: swapped order
        rois = (const int*)d_in[0];
        img  = (const float*)d_in[1];
    }
    float* out = (float*)d_out;

    dim3 grid(NUM_ROIS * POOL * POOL, NCHUNK);  // chunk = outer dim
    roi_resize_kernel<<<grid, THREADS>>>(img, rois, out);
}

// round 3
// speedup vs baseline: 1.5884x; 1.5884x over previous
#include <cuda_runtime.h>
#include <cstdint>

#define POOL 14
#define IMG_H 200
#define IMG_W 200
#define IMG_C 1024
#define NUM_ROIS 512

#define NCHUNK 4                       // 1024/4 = 256 ch -> 41MB image slice, L2-resident
#define CHUNK_FLOATS (IMG_C / NCHUNK)  // 256 floats
#define LANES_PER_CELL (CHUNK_FLOATS / 4)  // 64 threads, float4 each
#define CELLS_PER_BLOCK 4
#define THREADS (LANES_PER_CELL * CELLS_PER_BLOCK)  // 256

// grid = (cells/4, NCHUNK). Chunk is the outer dim so each 41MB channel slice
// stays L2-resident across all 512 ROIs. 256-thread CTAs (4 cells each) keep
// occupancy high (R2's 64-thread CTAs collapsed to 25% occ / 2.2TB/s).
__global__ void __launch_bounds__(THREADS, 8)
roi_resize_kernel(const float* __restrict__ img,
                  const int* __restrict__ rois,
                  float* __restrict__ out)
{
    const int cell_local = threadIdx.x >> 6;        // 0..3
    const int c          = threadIdx.x & 63;        // float4 lane within chunk

    const int idx  = blockIdx.x * CELLS_PER_BLOCK + cell_local;  // 0..100351
    const int roi  = idx / (POOL * POOL);
    const int cell = idx - roi * (POOL * POOL);
    const int py   = cell / POOL;
    const int px   = cell - py * POOL;

    const int chunk_off = blockIdx.y * CHUNK_FLOATS;

    const int4 box = reinterpret_cast<const int4*>(rois)[roi];
    const int bx = box.x, by = box.y, bw = box.z, bh = box.w;

    // Match reference math: fraction from UNclipped floor.
    const float sy = (float)py * ((float)bh / (float)POOL);
    const float sx = (float)px * ((float)bw / (float)POOL);
    const int y0 = (int)floorf(sy);
    const int x0 = (int)floorf(sx);
    const float wy = sy - (float)y0;
    const float wx = sx - (float)x0;

    const int y0c = min(max(y0, 0), bh - 1);
    const int y1c = min(max(y0 + 1, 0), bh - 1);
    const int x0c = min(max(x0, 0), bw - 1);
    const int x1c = min(max(x0 + 1, 0), bw - 1);

    const int iy0 = by + y0c;
    const int iy1 = by + y1c;
    const int ix0 = bx + x0c;
    const int ix1 = bx + x1c;

    const float* base = img + chunk_off;
    const float4* __restrict__ p00 =
        reinterpret_cast<const float4*>(base + ((size_t)iy0 * IMG_W + ix0) * IMG_C);
    const float4* __restrict__ p01 =
        reinterpret_cast<const float4*>(base + ((size_t)iy0 * IMG_W + ix1) * IMG_C);
    const float4* __restrict__ p10 =
        reinterpret_cast<const float4*>(base + ((size_t)iy1 * IMG_W + ix0) * IMG_C);
    const float4* __restrict__ p11 =
        reinterpret_cast<const float4*>(base + ((size_t)iy1 * IMG_W + ix1) * IMG_C);

    float4* __restrict__ o =
        reinterpret_cast<float4*>(out + (size_t)idx * IMG_C + chunk_off);

    const float4 g00 = p00[c];
    const float4 g01 = p01[c];
    const float4 g10 = p10[c];
    const float4 g11 = p11[c];

    float4 r;
    {
        float top, bot;
        top = g00.x + (g01.x - g00.x) * wx;
        bot = g10.x + (g11.x - g10.x) * wx;
        r.x = top + (bot - top) * wy;
        top = g00.y + (g01.y - g00.y) * wx;
        bot = g10.y + (g11.y - g10.y) * wx;
        r.y = top + (bot - top) * wy;
        top = g00.z + (g01.z - g00.z) * wx;
        bot = g10.z + (g11.z - g10.z) * wx;
        r.z = top + (bot - top) * wy;
        top = g00.w + (g01.w - g00.w) * wx;
        bot = g10.w + (g11.w - g10.w) * wx;
        r.w = top + (bot - top) * wy;
    }
    // Evict-first store: keep the output stream from evicting the image slice.
    __stcs(o + c, r);
}

extern "C" void kernel_launch(void* const* d_in, const int* in_sizes, int n_in,
                              void* d_out, int out_size)
{
    const float* img  = (const float*)d_in[0];
    const int*   rois = (const int*)d_in[1];
    if (in_sizes[0] == NUM_ROIS * 4) {  // defensive: swapped order
        rois = (const int*)d_in[0];
        img  = (const float*)d_in[1];
    }
    float* out = (float*)d_out;

    dim3 grid((NUM_ROIS * POOL * POOL) / CELLS_PER_BLOCK, NCHUNK);  // (25088, 4)
    roi_resize_kernel<<<grid, THREADS>>>(img, rois, out);
}

// round 4
// speedup vs baseline: 1.7289x; 1.0884x over previous
#include <cuda_runtime.h>
#include <cstdint>

#define POOL 14
#define IMG_H 200
#define IMG_W 200
#define IMG_C 1024
#define NUM_ROIS 512

#define NCHUNK 4                       // 1024/4 = 256 ch -> 41MB image slice, L2-resident
#define CHUNK_FLOATS (IMG_C / NCHUNK)  // 256 floats = 64 float4
#define LANES_PER_CELL 32              // each lane handles 2 float4 (c, c+32)
#define CELLS_PER_BLOCK 8
#define THREADS (LANES_PER_CELL * CELLS_PER_BLOCK)  // 256

// grid = (cells/8, NCHUNK). Chunk-outer keeps each 41MB channel slice
// L2-resident across all ROIs (traffic ~470MB total). Each lane moves
// 2 float4 per corner (8 LDG.128 in flight) to amortize setup and raise MLP.
__global__ void __launch_bounds__(THREADS)
roi_resize_kernel(const float* __restrict__ img,
                  const int* __restrict__ rois,
                  float* __restrict__ out)
{
    const int cell_local = threadIdx.x >> 5;        // 0..7
    const int c          = threadIdx.x & 31;        // float4 lane (first half)

    const int idx  = blockIdx.x * CELLS_PER_BLOCK + cell_local;  // 0..100351
    const int roi  = idx / (POOL * POOL);
    const int cell = idx - roi * (POOL * POOL);
    const int py   = cell / POOL;
    const int px   = cell - py * POOL;

    const int chunk_off = blockIdx.y * CHUNK_FLOATS;

    const int4 box = reinterpret_cast<const int4*>(rois)[roi];
    const int bx = box.x, by = box.y, bw = box.z, bh = box.w;

    // Match reference math: fraction from UNclipped floor.
    const float sy = (float)py * ((float)bh / (float)POOL);
    const float sx = (float)px * ((float)bw / (float)POOL);
    const int y0 = (int)floorf(sy);
    const int x0 = (int)floorf(sx);
    const float wy = sy - (float)y0;
    const float wx = sx - (float)x0;

    const int y0c = min(max(y0, 0), bh - 1);
    const int y1c = min(max(y0 + 1, 0), bh - 1);
    const int x0c = min(max(x0, 0), bw - 1);
    const int x1c = min(max(x0 + 1, 0), bw - 1);

    const int iy0 = by + y0c;
    const int iy1 = by + y1c;
    const int ix0 = bx + x0c;
    const int ix1 = bx + x1c;

    const float* base = img + chunk_off;
    const float4* __restrict__ p00 =
        reinterpret_cast<const float4*>(base + ((size_t)iy0 * IMG_W + ix0) * IMG_C);
    const float4* __restrict__ p01 =
        reinterpret_cast<const float4*>(base + ((size_t)iy0 * IMG_W + ix1) * IMG_C);
    const float4* __restrict__ p10 =
        reinterpret_cast<const float4*>(base + ((size_t)iy1 * IMG_W + ix0) * IMG_C);
    const float4* __restrict__ p11 =
        reinterpret_cast<const float4*>(base + ((size_t)iy1 * IMG_W + ix1) * IMG_C);

    float4* __restrict__ o =
        reinterpret_cast<float4*>(out + (size_t)idx * IMG_C + chunk_off);

    // 8 independent 16B loads, front-batched for MLP.
    const float4 a00 = p00[c];
    const float4 a01 = p01[c];
    const float4 a10 = p10[c];
    const float4 a11 = p11[c];
    const float4 b00 = p00[c + 32];
    const float4 b01 = p01[c + 32];
    const float4 b10 = p10[c + 32];
    const float4 b11 = p11[c + 32];

#define LERP1(r, g00v, g01v, g10v, g11v)                 \
    {                                                    \
        float top = g00v + (g01v - g00v) * wx;           \
        float bot = g10v + (g11v - g10v) * wx;           \
        r = top + (bot - top) * wy;                      \
    }

    float4 ra, rb;
    LERP1(ra.x, a00.x, a01.x, a10.x, a11.x);
    LERP1(ra.y, a00.y, a01.y, a10.y, a11.y);
    LERP1(ra.z, a00.z, a01.z, a10.z, a11.z);
    LERP1(ra.w, a00.w, a01.w, a10.w, a11.w);
    LERP1(rb.x, b00.x, b01.x, b10.x, b11.x);
    LERP1(rb.y, b00.y, b01.y, b10.y, b11.y);
    LERP1(rb.z, b00.z, b01.z, b10.z, b11.z);
    LERP1(rb.w, b00.w, b01.w, b10.w, b11.w);
#undef LERP1

    // Evict-first stores: keep the output stream from evicting the image slice.
    __stcs(o + c, ra);
    __stcs(o + c + 32, rb);
}

extern "C" void kernel_launch(void* const* d_in, const int* in_sizes, int n_in,
                              void* d_out, int out_size)
{
    const float* img  = (const float*)d_in[0];
    const int*   rois = (const int*)d_in[1];
    if (in_sizes[0] == NUM_ROIS * 4) {  // defensive: swapped order
        rois = (const int*)d_in[0];
        img  = (const float*)d_in[1];
    }
    float* out = (float*)d_out;

    dim3 grid((NUM_ROIS * POOL * POOL) / CELLS_PER_BLOCK, NCHUNK);  // (12544, 4)
    roi_resize_kernel<<<grid, THREADS>>>(img, rois, out);
}

// round 5
// speedup vs baseline: 1.8884x; 1.0922x over previous
#include <cuda_runtime.h>
#include <cstdint>

#define POOL 14
#define IMG_H 200
#define IMG_W 200
#define IMG_C 1024
#define NUM_ROIS 512

#define NCHUNK 4                       // 256-ch slices -> 41MB image slice, L2-resident
#define CHUNK_FLOATS (IMG_C / NCHUNK)  // 256 floats = 64 float4
#define LANES_PER_CELL 16              // each lane handles 4 float4 (c, c+16, c+32, c+48)
#define CELLS_PER_BLOCK 16
#define THREADS (LANES_PER_CELL * CELLS_PER_BLOCK)  // 256

// ---- packed f32x2 helpers (sm_103a) ----
__device__ __forceinline__ unsigned long long pk2(float a, float b) {
    unsigned long long r;
    asm("mov.b64 %0, {%1, %2};" : "=l"(r) : "f"(a), "f"(b));
    return r;
}
__device__ __forceinline__ void unpk2(float& a, float& b, unsigned long long v) {
    asm("mov.b64 {%0, %1}, %2;" : "=f"(a), "=f"(b) : "l"(v));
}
__device__ __forceinline__ unsigned long long mul2(unsigned long long a, unsigned long long b) {
    unsigned long long r;
    asm("mul.rn.f32x2 %0, %1, %2;" : "=l"(r) : "l"(a), "l"(b));
    return r;
}
__device__ __forceinline__ unsigned long long fma2(unsigned long long a, unsigned long long b,
                                                   unsigned long long c) {
    unsigned long long r;
    asm("fma.rn.f32x2 %0, %1, %2, %3;" : "=l"(r) : "l"(a), "l"(b), "l"(c));
    return r;
}

// grid = (cells/16, NCHUNK). Chunk-outer keeps each 41MB channel slice
// L2-resident across all ROIs (~470MB total DRAM traffic). Each lane moves
// 4 float4 in two 8-load batches; interpolation uses packed f32x2 FMA.
__global__ void __launch_bounds__(THREADS)
roi_resize_kernel(const float* __restrict__ img,
                  const int* __restrict__ rois,
                  float* __restrict__ out)
{
    const int cell_local = threadIdx.x >> 4;        // 0..15
    const int c          = threadIdx.x & 15;        // float4 lane base

    const int idx  = blockIdx.x * CELLS_PER_BLOCK + cell_local;  // 0..100351
    const int roi  = idx / (POOL * POOL);
    const int cell = idx - roi * (POOL * POOL);
    const int py   = cell / POOL;
    const int px   = cell - py * POOL;

    const int chunk_off = blockIdx.y * CHUNK_FLOATS;

    const int4 box = reinterpret_cast<const int4*>(rois)[roi];
    const int bx = box.x, by = box.y, bw = box.z, bh = box.w;

    // Match reference math: fraction from UNclipped floor.
    const float sy = (float)py * ((float)bh / (float)POOL);
    const float sx = (float)px * ((float)bw / (float)POOL);
    const int y0 = (int)floorf(sy);
    const int x0 = (int)floorf(sx);
    const float wy = sy - (float)y0;
    const float wx = sx - (float)x0;

    const int y0c = min(max(y0, 0), bh - 1);
    const int y1c = min(max(y0 + 1, 0), bh - 1);
    const int x0c = min(max(x0, 0), bw - 1);
    const int x1c = min(max(x0 + 1, 0), bw - 1);

    const int iy0 = by + y0c;
    const int iy1 = by + y1c;
    const int ix0 = bx + x0c;
    const int ix1 = bx + x1c;

    const unsigned long long wx2   = pk2(wx, wx);
    const unsigned long long omwx2 = pk2(1.0f - wx, 1.0f - wx);
    const unsigned long long wy2   = pk2(wy, wy);
    const unsigned long long omwy2 = pk2(1.0f - wy, 1.0f - wy);

    const float* base = img + chunk_off;
    const float4* __restrict__ p00 =
        reinterpret_cast<const float4*>(base + ((size_t)iy0 * IMG_W + ix0) * IMG_C);
    const float4* __restrict__ p01 =
        reinterpret_cast<const float4*>(base + ((size_t)iy0 * IMG_W + ix1) * IMG_C);
    const float4* __restrict__ p10 =
        reinterpret_cast<const float4*>(base + ((size_t)iy1 * IMG_W + ix0) * IMG_C);
    const float4* __restrict__ p11 =
        reinterpret_cast<const float4*>(base + ((size_t)iy1 * IMG_W + ix1) * IMG_C);

    float4* __restrict__ o =
        reinterpret_cast<float4*>(out + (size_t)idx * IMG_C + chunk_off);

    // lerp of one packed pair: r = (g00*(1-wx) + g01*wx)*(1-wy) + (g10*(1-wx) + g11*wx)*wy
#define LERP2(g00v, g01v, g10v, g11v)                                        \
    fma2(fma2(g11v, wx2, mul2(g10v, omwx2)), wy2,                            \
         mul2(fma2(g01v, wx2, mul2(g00v, omwx2)), omwy2))

    // Two batches of 8 front-batched LDG.128 (keeps regs ~R4 level, MLP=8).
#pragma unroll
    for (int h = 0; h < 2; h++) {
        const int o0 = c + h * 32;       // first float4 of batch
        const int o1 = o0 + 16;          // second float4 of batch

        const float4 a00 = p00[o0];
        const float4 a01 = p01[o0];
        const float4 a10 = p10[o0];
        const float4 a11 = p11[o0];
        const float4 b00 = p00[o1];
        const float4 b01 = p01[o1];
        const float4 b10 = p10[o1];
        const float4 b11 = p11[o1];

        unsigned long long ra_lo = LERP2(pk2(a00.x, a00.y), pk2(a01.x, a01.y),
                                         pk2(a10.x, a10.y), pk2(a11.x, a11.y));
        unsigned long long ra_hi = LERP2(pk2(a00.z, a00.w), pk2(a01.z, a01.w),
                                         pk2(a10.z, a10.w), pk2(a11.z, a11.w));
        unsigned long long rb_lo = LERP2(pk2(b00.x, b00.y), pk2(b01.x, b01.y),
                                         pk2(b10.x, b10.y), pk2(b11.x, b11.y));
        unsigned long long rb_hi = LERP2(pk2(b00.z, b00.w), pk2(b01.z, b01.w),
                                         pk2(b10.z, b10.w), pk2(b11.z, b11.w));

        float4 ra, rb;
        unpk2(ra.x, ra.y, ra_lo);
        unpk2(ra.z, ra.w, ra_hi);
        unpk2(rb.x, rb.y, rb_lo);
        unpk2(rb.z, rb.w, rb_hi);

        // Evict-first stores: keep the output stream from evicting the image slice.
        __stcs(o + o0, ra);
        __stcs(o + o1, rb);
    }
#undef LERP2
}

extern "C" void kernel_launch(void* const* d_in, const int* in_sizes, int n_in,
                              void* d_out, int out_size)
{
    const float* img  = (const float*)d_in[0];
    const int*   rois = (const int*)d_in[1];
    if (in_sizes[0] == NUM_ROIS * 4) {  // defensive: swapped order
        rois = (const int*)d_in[0];
        img  = (const float*)d_in[1];
    }
    float* out = (float*)d_out;

    dim3 grid((NUM_ROIS * POOL * POOL) / CELLS_PER_BLOCK, NCHUNK);  // (6272, 4)
    roi_resize_kernel<<<grid, THREADS>>>(img, rois, out);
}